// round 1
// baseline (speedup 1.0000x reference)
#include <cuda_runtime.h>
#include <cuda_bf16.h>

#define D_MODEL   1024
#define NUM_HEADS 16
#define D_K       64
#define BATCH     4
#define SEQ       2048
#define M_TOKENS  (BATCH * SEQ)   // 8192

// ---------------------------------------------------------------------------
// Scratch (allocation-free per harness rules): Q, K, V in [b, h, s, 64] layout,
// attention output O in merged [b, s, 1024] layout.
// ---------------------------------------------------------------------------
__device__ float g_q[BATCH * NUM_HEADS * SEQ * D_K];
__device__ float g_k[BATCH * NUM_HEADS * SEQ * D_K];
__device__ float g_v[BATCH * NUM_HEADS * SEQ * D_K];
__device__ float g_o[M_TOKENS * D_MODEL];

// ---------------------------------------------------------------------------
// GEMM: C[m,n] = sum_k A[m,k] * B[n,k]   (A: [M,K] row-major, B: [N,K] row-major)
// Tiles: BM=64, BN=64, BK=32. 256 threads, 4x4 microtile per thread.
// splitHeads=1: write C to [b, h, s, d_k] layout (for Q/K/V projections).
// splitHeads=0: write C to plain [M, N] row-major (output projection).
// ---------------------------------------------------------------------------
__global__ __launch_bounds__(256, 4)
void gemm_nt(const float* __restrict__ A, const float* __restrict__ B,
             float* __restrict__ C, int K, int splitHeads)
{
    __shared__ float As[32][68];   // [k][m], padded
    __shared__ float Bs[32][68];   // [k][n], padded

    const int tid = threadIdx.x;
    const int tx  = tid & 15;      // 0..15 -> n microtile
    const int ty  = tid >> 4;      // 0..15 -> m microtile

    const int m0 = blockIdx.y * 64;
    const int n0 = blockIdx.x * 64;

    float acc[4][4];
#pragma unroll
    for (int i = 0; i < 4; ++i)
#pragma unroll
        for (int j = 0; j < 4; ++j) acc[i][j] = 0.0f;

    for (int k0 = 0; k0 < K; k0 += 32) {
        // Load 64x32 tiles of A and B (each as 512 float4, 2 per thread),
        // storing transposed into shared.
#pragma unroll
        for (int l = 0; l < 2; ++l) {
            int idx = tid + l * 256;
            int row = idx >> 3;        // 0..63
            int c4  = idx & 7;         // 0..7
            float4 va = *(const float4*)&A[(size_t)(m0 + row) * K + k0 + c4 * 4];
            As[c4 * 4 + 0][row] = va.x;
            As[c4 * 4 + 1][row] = va.y;
            As[c4 * 4 + 2][row] = va.z;
            As[c4 * 4 + 3][row] = va.w;
            float4 vb = *(const float4*)&B[(size_t)(n0 + row) * K + k0 + c4 * 4];
            Bs[c4 * 4 + 0][row] = vb.x;
            Bs[c4 * 4 + 1][row] = vb.y;
            Bs[c4 * 4 + 2][row] = vb.z;
            Bs[c4 * 4 + 3][row] = vb.w;
        }
        __syncthreads();

#pragma unroll
        for (int k = 0; k < 32; ++k) {
            float a[4], b[4];
#pragma unroll
            for (int i = 0; i < 4; ++i) a[i] = As[k][ty * 4 + i];
#pragma unroll
            for (int j = 0; j < 4; ++j) b[j] = Bs[k][tx * 4 + j];
#pragma unroll
            for (int i = 0; i < 4; ++i)
#pragma unroll
                for (int j = 0; j < 4; ++j)
                    acc[i][j] = fmaf(a[i], b[j], acc[i][j]);
        }
        __syncthreads();
    }

    if (splitHeads) {
#pragma unroll
        for (int i = 0; i < 4; ++i) {
            int m = m0 + ty * 4 + i;
            int b = m >> 11;           // m / SEQ
            int s = m & (SEQ - 1);
#pragma unroll
            for (int j = 0; j < 4; ++j) {
                int n = n0 + tx * 4 + j;
                int h = n >> 6;
                int d = n & 63;
                C[((size_t)(b * NUM_HEADS + h) * SEQ + s) * D_K + d] = acc[i][j];
            }
        }
    } else {
#pragma unroll
        for (int i = 0; i < 4; ++i) {
            int m = m0 + ty * 4 + i;
#pragma unroll
            for (int j = 0; j < 4; ++j) {
                int n = n0 + tx * 4 + j;
                C[(size_t)m * D_MODEL + n] = acc[i][j];
            }
        }
    }
}

// ---------------------------------------------------------------------------
// Flash attention (causal, fp32, online softmax).
// Q/K/V: [b*h][s][64]. Output written directly in merged [b, s, 1024] layout.
// BM = BN = 64, 256 threads, 4x4 microtiles for both S=QK^T and O+=P@V.
// Dynamic smem: Qs + Ks + Vs + Ps = 4 * 64*68*4 = 69632 B.
// ---------------------------------------------------------------------------
#define ATT_STRIDE 68
#define ATT_SMEM_BYTES (4 * 64 * ATT_STRIDE * 4)

__global__ __launch_bounds__(256, 2)
void flash_attn(const float* __restrict__ Q, const float* __restrict__ K,
                const float* __restrict__ V, float* __restrict__ O)
{
    extern __shared__ float smem[];
    float* Qs = smem;                      // [64][68]
    float* Ks = Qs + 64 * ATT_STRIDE;      // [64][68]
    float* Vs = Ks + 64 * ATT_STRIDE;      // [64][68]
    float* Ps = Vs + 64 * ATT_STRIDE;      // [64][68]

    const int tid = threadIdx.x;
    const int tx  = tid & 15;
    const int ty  = tid >> 4;

    const int bh = blockIdx.y;             // 0..63
    const int b  = bh / NUM_HEADS;
    const int h  = bh % NUM_HEADS;
    const int i0 = blockIdx.x * 64;        // query tile start

    const float* Qb = Q + (size_t)bh * SEQ * D_K;
    const float* Kb = K + (size_t)bh * SEQ * D_K;
    const float* Vb = V + (size_t)bh * SEQ * D_K;

    // Load Q tile (64 rows x 64 floats = 1024 float4, 4 per thread)
#pragma unroll
    for (int l = 0; l < 4; ++l) {
        int idx = tid + l * 256;
        int row = idx >> 4;                // 0..63
        int c4  = idx & 15;
        float4 v = *(const float4*)&Qb[(size_t)(i0 + row) * D_K + c4 * 4];
        *(float4*)&Qs[row * ATT_STRIDE + c4 * 4] = v;
    }

    float m_i[4], l_i[4], o[4][4];
#pragma unroll
    for (int i = 0; i < 4; ++i) {
        m_i[i] = -1e30f;
        l_i[i] = 0.0f;
#pragma unroll
        for (int j = 0; j < 4; ++j) o[i][j] = 0.0f;
    }

    for (int j0 = 0; j0 <= i0; j0 += 64) {
        // Load K and V tiles
#pragma unroll
        for (int l = 0; l < 4; ++l) {
            int idx = tid + l * 256;
            int row = idx >> 4;
            int c4  = idx & 15;
            float4 vk = *(const float4*)&Kb[(size_t)(j0 + row) * D_K + c4 * 4];
            *(float4*)&Ks[row * ATT_STRIDE + c4 * 4] = vk;
            float4 vv = *(const float4*)&Vb[(size_t)(j0 + row) * D_K + c4 * 4];
            *(float4*)&Vs[row * ATT_STRIDE + c4 * 4] = vv;
        }
        __syncthreads();

        // S = Q @ K^T (4x4 per thread)
        float s_acc[4][4];
#pragma unroll
        for (int i = 0; i < 4; ++i)
#pragma unroll
            for (int j = 0; j < 4; ++j) s_acc[i][j] = 0.0f;

#pragma unroll 8
        for (int d = 0; d < 64; ++d) {
            float q[4], kk[4];
#pragma unroll
            for (int i = 0; i < 4; ++i) q[i]  = Qs[(ty * 4 + i) * ATT_STRIDE + d];
#pragma unroll
            for (int j = 0; j < 4; ++j) kk[j] = Ks[(tx * 4 + j) * ATT_STRIDE + d];
#pragma unroll
            for (int i = 0; i < 4; ++i)
#pragma unroll
                for (int j = 0; j < 4; ++j)
                    s_acc[i][j] = fmaf(q[i], kk[j], s_acc[i][j]);
        }

        // scale + causal mask (only the diagonal tile can mask)
        const bool diag = (j0 == i0);
#pragma unroll
        for (int i = 0; i < 4; ++i) {
            int qi = ty * 4 + i;           // local row == global offset match on diag tile
#pragma unroll
            for (int j = 0; j < 4; ++j) {
                float sv = s_acc[i][j] * 0.125f;   // 1/sqrt(64)
                if (diag && (tx * 4 + j > qi)) sv = -1e30f;
                s_acc[i][j] = sv;
            }
        }

        // online softmax update
        float mnew[4], alpha[4];
#pragma unroll
        for (int i = 0; i < 4; ++i) {
            float lm = fmaxf(fmaxf(s_acc[i][0], s_acc[i][1]),
                             fmaxf(s_acc[i][2], s_acc[i][3]));
#pragma unroll
            for (int off = 8; off >= 1; off >>= 1)
                lm = fmaxf(lm, __shfl_xor_sync(0xffffffffu, lm, off));
            mnew[i]  = fmaxf(m_i[i], lm);
            alpha[i] = __expf(m_i[i] - mnew[i]);
            m_i[i]   = mnew[i];
        }

#pragma unroll
        for (int i = 0; i < 4; ++i) {
            float rs = 0.0f;
#pragma unroll
            for (int j = 0; j < 4; ++j) {
                float p = __expf(s_acc[i][j] - mnew[i]);
                Ps[(ty * 4 + i) * ATT_STRIDE + tx * 4 + j] = p;
                rs += p;
            }
#pragma unroll
            for (int off = 8; off >= 1; off >>= 1)
                rs += __shfl_xor_sync(0xffffffffu, rs, off);
            l_i[i] = l_i[i] * alpha[i] + rs;
        }

#pragma unroll
        for (int i = 0; i < 4; ++i)
#pragma unroll
            for (int j = 0; j < 4; ++j) o[i][j] *= alpha[i];

        __syncthreads();   // Ps visible to all

        // O += P @ V
#pragma unroll 8
        for (int c = 0; c < 64; ++c) {
            float p[4], v[4];
#pragma unroll
            for (int i = 0; i < 4; ++i) p[i] = Ps[(ty * 4 + i) * ATT_STRIDE + c];
#pragma unroll
            for (int j = 0; j < 4; ++j) v[j] = Vs[c * ATT_STRIDE + tx * 4 + j];
#pragma unroll
            for (int i = 0; i < 4; ++i)
#pragma unroll
                for (int j = 0; j < 4; ++j)
                    o[i][j] = fmaf(p[i], v[j], o[i][j]);
        }
        __syncthreads();   // done reading Ks/Vs/Ps before next tile load
    }

    // epilogue: normalize and write merged [b, s, h*64 + d] layout
#pragma unroll
    for (int i = 0; i < 4; ++i) {
        int row = i0 + ty * 4 + i;
        float inv_l = 1.0f / l_i[i];
#pragma unroll
        for (int j = 0; j < 4; ++j) {
            O[((size_t)(b * SEQ + row)) * D_MODEL + h * D_K + tx * 4 + j] =
                o[i][j] * inv_l;
        }
    }
}

// ---------------------------------------------------------------------------
// Launch
// ---------------------------------------------------------------------------
extern "C" void kernel_launch(void* const* d_in, const int* in_sizes, int n_in,
                              void* d_out, int out_size)
{
    const float* x  = (const float*)d_in[0];
    const float* wq = (const float*)d_in[1];
    const float* wk = (const float*)d_in[2];
    const float* wv = (const float*)d_in[3];
    const float* wo = (const float*)d_in[4];
    float* out = (float*)d_out;

    float *q, *k, *v, *o;
    cudaGetSymbolAddress((void**)&q, g_q);
    cudaGetSymbolAddress((void**)&k, g_k);
    cudaGetSymbolAddress((void**)&v, g_v);
    cudaGetSymbolAddress((void**)&o, g_o);

    cudaFuncSetAttribute(flash_attn, cudaFuncAttributeMaxDynamicSharedMemorySize,
                         ATT_SMEM_BYTES);

    dim3 gemmGrid(D_MODEL / 64, M_TOKENS / 64);   // (16, 128)

    gemm_nt<<<gemmGrid, 256>>>(x, wq, q, D_MODEL, 1);
    gemm_nt<<<gemmGrid, 256>>>(x, wk, k, D_MODEL, 1);
    gemm_nt<<<gemmGrid, 256>>>(x, wv, v, D_MODEL, 1);

    dim3 attnGrid(SEQ / 64, BATCH * NUM_HEADS);   // (32, 64)
    flash_attn<<<attnGrid, 256, ATT_SMEM_BYTES>>>(q, k, v, o);

    gemm_nt<<<gemmGrid, 256>>>(o, wo, out, D_MODEL, 0);
}

// round 4
// speedup vs baseline: 1.4774x; 1.4774x over previous
#include <cuda_runtime.h>
#include <cuda_bf16.h>
#include <cstdint>

#define D_MODEL   1024
#define NUM_HEADS 16
#define D_K       64
#define BATCH     4
#define SEQ       2048
#define M_TOKENS  (BATCH * SEQ)          // 8192
#define NELEM     (M_TOKENS * D_MODEL)   // 8388608
#define W_ELEM    (D_MODEL * D_MODEL)    // 1048576

// ---------------------------------------------------------------------------
// Scratch (allocation-free)
// ---------------------------------------------------------------------------
__device__ __nv_bfloat16 g_xhi[NELEM],  g_xlo[NELEM];
__device__ __nv_bfloat16 g_wqhi[W_ELEM], g_wqlo[W_ELEM];
__device__ __nv_bfloat16 g_wkhi[W_ELEM], g_wklo[W_ELEM];
__device__ __nv_bfloat16 g_wvhi[W_ELEM], g_wvlo[W_ELEM];
__device__ __nv_bfloat16 g_wohi[W_ELEM], g_wolo[W_ELEM];
__device__ float g_q[NELEM], g_k[NELEM], g_v[NELEM], g_o[NELEM];
__device__ __nv_bfloat16 g_ohi[NELEM],  g_olo[NELEM];

// ---------------------------------------------------------------------------
// fp32 -> (bf16 hi, bf16 lo) split
// ---------------------------------------------------------------------------
__global__ void prep_split(const float* __restrict__ in,
                           __nv_bfloat16* __restrict__ hi,
                           __nv_bfloat16* __restrict__ lo, int n4)
{
    int i = blockIdx.x * blockDim.x + threadIdx.x;
    if (i >= n4) return;
    float4 f = ((const float4*)in)[i];
    float fv[4] = {f.x, f.y, f.z, f.w};
    __nv_bfloat16 h[4], l[4];
#pragma unroll
    for (int j = 0; j < 4; ++j) {
        h[j] = __float2bfloat16(fv[j]);
        l[j] = __float2bfloat16(fv[j] - __bfloat162float(h[j]));
    }
    ((uint2*)hi)[i] = *(uint2*)h;
    ((uint2*)lo)[i] = *(uint2*)l;
}

// ---------------------------------------------------------------------------
// HMMA helpers
// ---------------------------------------------------------------------------
__device__ __forceinline__ void mma16816(float* c, const uint32_t* a,
                                         const uint32_t* b)
{
    asm volatile(
        "mma.sync.aligned.m16n8k16.row.col.f32.bf16.bf16.f32 "
        "{%0,%1,%2,%3}, {%4,%5,%6,%7}, {%8,%9}, {%0,%1,%2,%3};"
        : "+f"(c[0]), "+f"(c[1]), "+f"(c[2]), "+f"(c[3])
        : "r"(a[0]), "r"(a[1]), "r"(a[2]), "r"(a[3]),
          "r"(b[0]), "r"(b[1]));
}

__device__ __forceinline__ uint32_t smem_u32(const void* p) {
    uint32_t a;
    asm("{ .reg .u64 t; cvta.to.shared.u64 t, %1; cvt.u32.u64 %0, t; }"
        : "=r"(a) : "l"(p));
    return a;
}
__device__ __forceinline__ void cp_async16(uint32_t dst, const void* src) {
    asm volatile("cp.async.cg.shared.global [%0], [%1], 16;"
                 :: "r"(dst), "l"(src) : "memory");
}
__device__ __forceinline__ void cp_commit() {
    asm volatile("cp.async.commit_group;" ::: "memory");
}
template <int N>
__device__ __forceinline__ void cp_wait() {
    asm volatile("cp.async.wait_group %0;" :: "n"(N) : "memory");
}

// ---------------------------------------------------------------------------
// HMMA GEMM: C[m,n] = sum_k A[m,k]*B[n,k], fp32-accurate via bf16 hi/lo
// (A*B ~= Ahi*Bhi + Ahi*Blo + Alo*Bhi). CTA 128x128, BK=32, 256 threads.
// Warp grid 2(m) x 4(n); warp tile 64x32 -> 4x4 m16n8 fragments.
// Double-buffered cp.async stages; smem row stride 40 bf16 (conflict-free).
// ---------------------------------------------------------------------------
#define BK        32
#define SROW      40                          // 32 + 8 pad (bf16)
#define TILE_B    (128 * SROW * 2)            // 10240 bytes
#define STAGE_B   (4 * TILE_B)                // Ahi, Alo, Bhi, Blo = 40960
#define GEMM_SMEM (2 * STAGE_B)               // 81920
#define NK_CHUNKS (D_MODEL / BK)              // 32

__global__ __launch_bounds__(256, 1)
void gemm_tc(const __nv_bfloat16* __restrict__ Ahi,
             const __nv_bfloat16* __restrict__ Alo,
             const __nv_bfloat16* __restrict__ Bhi,
             const __nv_bfloat16* __restrict__ Blo,
             float* __restrict__ C, int splitHeads)
{
    extern __shared__ __align__(16) char sm[];

    const int tid  = threadIdx.x;
    const int wid  = tid >> 5;
    const int lane = tid & 31;
    const int grp  = lane >> 2;          // 0..7
    const int qp   = lane & 3;           // 0..3

    const int warp_m = (wid & 1) * 64;   // 0 or 64
    const int warp_n = (wid >> 1) * 32;  // 0,32,64,96

    const int m0 = blockIdx.y * 128;
    const int n0 = blockIdx.x * 128;

    const __nv_bfloat16* srcs[4] = {
        Ahi + (size_t)m0 * D_MODEL, Alo + (size_t)m0 * D_MODEL,
        Bhi + (size_t)n0 * D_MODEL, Blo + (size_t)n0 * D_MODEL
    };

    const uint32_t smbase = smem_u32(sm);

    // Load one BK chunk (4 tiles of 128 rows x 32 bf16) into a stage.
    auto load_stage = [&](int stage, int k0) {
        uint32_t dst0 = smbase + stage * STAGE_B;
#pragma unroll
        for (int a = 0; a < 4; ++a) {
#pragma unroll
            for (int it = 0; it < 2; ++it) {
                int g   = tid + it * 256;      // 0..511
                int row = g >> 2;
                int q   = g & 3;
                const __nv_bfloat16* src = srcs[a] + (size_t)row * D_MODEL + k0 + q * 8;
                cp_async16(dst0 + a * TILE_B + (row * SROW + q * 8) * 2, src);
            }
        }
        cp_commit();
    };

    float acc[4][4][4];
#pragma unroll
    for (int mf = 0; mf < 4; ++mf)
#pragma unroll
        for (int nf = 0; nf < 4; ++nf)
#pragma unroll
            for (int r = 0; r < 4; ++r) acc[mf][nf][r] = 0.0f;

    load_stage(0, 0);
    load_stage(1, BK);

    for (int kc = 0; kc < NK_CHUNKS; ++kc) {
        // Drain: while a younger group exists, wait_group 1 suffices (leaves
        // the younger one in flight). On the last two chunks there is no
        // younger group, so wait_group 0 is required for chunk kc itself.
        if (kc < NK_CHUNKS - 2) cp_wait<1>();
        else                    cp_wait<0>();
        __syncthreads();

        const int st = kc & 1;
        const __nv_bfloat16* Ahs = (const __nv_bfloat16*)(sm + st * STAGE_B);
        const __nv_bfloat16* Als = Ahs + 128 * SROW;
        const __nv_bfloat16* Bhs = Als + 128 * SROW;
        const __nv_bfloat16* Bls = Bhs + 128 * SROW;

#pragma unroll
        for (int ks = 0; ks < 2; ++ks) {
            const int kb = ks * 16;
            uint32_t ahi[4][4], alo[4][4], bhi[4][2], blo[4][2];
#pragma unroll
            for (int mf = 0; mf < 4; ++mf) {
                int r0 = warp_m + mf * 16 + grp;
                int c0 = kb + qp * 2;
                ahi[mf][0] = *(const uint32_t*)&Ahs[r0 * SROW + c0];
                ahi[mf][1] = *(const uint32_t*)&Ahs[(r0 + 8) * SROW + c0];
                ahi[mf][2] = *(const uint32_t*)&Ahs[r0 * SROW + c0 + 8];
                ahi[mf][3] = *(const uint32_t*)&Ahs[(r0 + 8) * SROW + c0 + 8];
                alo[mf][0] = *(const uint32_t*)&Als[r0 * SROW + c0];
                alo[mf][1] = *(const uint32_t*)&Als[(r0 + 8) * SROW + c0];
                alo[mf][2] = *(const uint32_t*)&Als[r0 * SROW + c0 + 8];
                alo[mf][3] = *(const uint32_t*)&Als[(r0 + 8) * SROW + c0 + 8];
            }
#pragma unroll
            for (int nf = 0; nf < 4; ++nf) {
                int n = warp_n + nf * 8 + grp;
                int c0 = kb + qp * 2;
                bhi[nf][0] = *(const uint32_t*)&Bhs[n * SROW + c0];
                bhi[nf][1] = *(const uint32_t*)&Bhs[n * SROW + c0 + 8];
                blo[nf][0] = *(const uint32_t*)&Bls[n * SROW + c0];
                blo[nf][1] = *(const uint32_t*)&Bls[n * SROW + c0 + 8];
            }
#pragma unroll
            for (int mf = 0; mf < 4; ++mf)
#pragma unroll
                for (int nf = 0; nf < 4; ++nf) {
                    mma16816(acc[mf][nf], ahi[mf], bhi[nf]);
                    mma16816(acc[mf][nf], ahi[mf], blo[nf]);
                    mma16816(acc[mf][nf], alo[mf], bhi[nf]);
                }
        }
        __syncthreads();
        if (kc + 2 < NK_CHUNKS) load_stage(st, (kc + 2) * BK);
    }

    // Epilogue
#pragma unroll
    for (int mf = 0; mf < 4; ++mf) {
#pragma unroll
        for (int half = 0; half < 2; ++half) {
            int m = m0 + warp_m + mf * 16 + grp + half * 8;
            if (splitHeads) {
                int b = m >> 11, s = m & (SEQ - 1);
#pragma unroll
                for (int nf = 0; nf < 4; ++nf) {
                    int n = n0 + warp_n + nf * 8 + qp * 2;
                    int h = n >> 6, d = n & 63;
                    float2 v = make_float2(acc[mf][nf][half * 2],
                                           acc[mf][nf][half * 2 + 1]);
                    *(float2*)&C[((size_t)(b * NUM_HEADS + h) * SEQ + s) * D_K + d] = v;
                }
            } else {
#pragma unroll
                for (int nf = 0; nf < 4; ++nf) {
                    int n = n0 + warp_n + nf * 8 + qp * 2;
                    float2 v = make_float2(acc[mf][nf][half * 2],
                                           acc[mf][nf][half * 2 + 1]);
                    *(float2*)&C[(size_t)m * D_MODEL + n] = v;
                }
            }
        }
    }
}

// ---------------------------------------------------------------------------
// Flash attention (causal, fp32, online softmax) — unchanged from round 1.
// ---------------------------------------------------------------------------
#define ATT_STRIDE 68
#define ATT_SMEM_BYTES (4 * 64 * ATT_STRIDE * 4)

__global__ __launch_bounds__(256, 2)
void flash_attn(const float* __restrict__ Q, const float* __restrict__ K,
                const float* __restrict__ V, float* __restrict__ O)
{
    extern __shared__ float smem[];
    float* Qs = smem;
    float* Ks = Qs + 64 * ATT_STRIDE;
    float* Vs = Ks + 64 * ATT_STRIDE;
    float* Ps = Vs + 64 * ATT_STRIDE;

    const int tid = threadIdx.x;
    const int tx  = tid & 15;
    const int ty  = tid >> 4;

    const int bh = blockIdx.y;
    const int b  = bh / NUM_HEADS;
    const int h  = bh % NUM_HEADS;
    const int i0 = blockIdx.x * 64;

    const float* Qb = Q + (size_t)bh * SEQ * D_K;
    const float* Kb = K + (size_t)bh * SEQ * D_K;
    const float* Vb = V + (size_t)bh * SEQ * D_K;

#pragma unroll
    for (int l = 0; l < 4; ++l) {
        int idx = tid + l * 256;
        int row = idx >> 4;
        int c4  = idx & 15;
        float4 v = *(const float4*)&Qb[(size_t)(i0 + row) * D_K + c4 * 4];
        *(float4*)&Qs[row * ATT_STRIDE + c4 * 4] = v;
    }

    float m_i[4], l_i[4], o[4][4];
#pragma unroll
    for (int i = 0; i < 4; ++i) {
        m_i[i] = -1e30f; l_i[i] = 0.0f;
#pragma unroll
        for (int j = 0; j < 4; ++j) o[i][j] = 0.0f;
    }

    for (int j0 = 0; j0 <= i0; j0 += 64) {
#pragma unroll
        for (int l = 0; l < 4; ++l) {
            int idx = tid + l * 256;
            int row = idx >> 4;
            int c4  = idx & 15;
            float4 vk = *(const float4*)&Kb[(size_t)(j0 + row) * D_K + c4 * 4];
            *(float4*)&Ks[row * ATT_STRIDE + c4 * 4] = vk;
            float4 vv = *(const float4*)&Vb[(size_t)(j0 + row) * D_K + c4 * 4];
            *(float4*)&Vs[row * ATT_STRIDE + c4 * 4] = vv;
        }
        __syncthreads();

        float s_acc[4][4];
#pragma unroll
        for (int i = 0; i < 4; ++i)
#pragma unroll
            for (int j = 0; j < 4; ++j) s_acc[i][j] = 0.0f;

#pragma unroll 8
        for (int d = 0; d < 64; ++d) {
            float q[4], kk[4];
#pragma unroll
            for (int i = 0; i < 4; ++i) q[i]  = Qs[(ty * 4 + i) * ATT_STRIDE + d];
#pragma unroll
            for (int j = 0; j < 4; ++j) kk[j] = Ks[(tx * 4 + j) * ATT_STRIDE + d];
#pragma unroll
            for (int i = 0; i < 4; ++i)
#pragma unroll
                for (int j = 0; j < 4; ++j)
                    s_acc[i][j] = fmaf(q[i], kk[j], s_acc[i][j]);
        }

        const bool diag = (j0 == i0);
#pragma unroll
        for (int i = 0; i < 4; ++i) {
            int qi = ty * 4 + i;
#pragma unroll
            for (int j = 0; j < 4; ++j) {
                float sv = s_acc[i][j] * 0.125f;
                if (diag && (tx * 4 + j > qi)) sv = -1e30f;
                s_acc[i][j] = sv;
            }
        }

        float mnew[4], alpha[4];
#pragma unroll
        for (int i = 0; i < 4; ++i) {
            float lm = fmaxf(fmaxf(s_acc[i][0], s_acc[i][1]),
                             fmaxf(s_acc[i][2], s_acc[i][3]));
#pragma unroll
            for (int off = 8; off >= 1; off >>= 1)
                lm = fmaxf(lm, __shfl_xor_sync(0xffffffffu, lm, off));
            mnew[i]  = fmaxf(m_i[i], lm);
            alpha[i] = __expf(m_i[i] - mnew[i]);
            m_i[i]   = mnew[i];
        }

#pragma unroll
        for (int i = 0; i < 4; ++i) {
            float rs = 0.0f;
#pragma unroll
            for (int j = 0; j < 4; ++j) {
                float p = __expf(s_acc[i][j] - mnew[i]);
                Ps[(ty * 4 + i) * ATT_STRIDE + tx * 4 + j] = p;
                rs += p;
            }
#pragma unroll
            for (int off = 8; off >= 1; off >>= 1)
                rs += __shfl_xor_sync(0xffffffffu, rs, off);
            l_i[i] = l_i[i] * alpha[i] + rs;
        }

#pragma unroll
        for (int i = 0; i < 4; ++i)
#pragma unroll
            for (int j = 0; j < 4; ++j) o[i][j] *= alpha[i];

        __syncthreads();

#pragma unroll 8
        for (int c = 0; c < 64; ++c) {
            float p[4], v[4];
#pragma unroll
            for (int i = 0; i < 4; ++i) p[i] = Ps[(ty * 4 + i) * ATT_STRIDE + c];
#pragma unroll
            for (int j = 0; j < 4; ++j) v[j] = Vs[c * ATT_STRIDE + tx * 4 + j];
#pragma unroll
            for (int i = 0; i < 4; ++i)
#pragma unroll
                for (int j = 0; j < 4; ++j)
                    o[i][j] = fmaf(p[i], v[j], o[i][j]);
        }
        __syncthreads();
    }

#pragma unroll
    for (int i = 0; i < 4; ++i) {
        int row = i0 + ty * 4 + i;
        float inv_l = 1.0f / l_i[i];
#pragma unroll
        for (int j = 0; j < 4; ++j) {
            O[((size_t)(b * SEQ + row)) * D_MODEL + h * D_K + tx * 4 + j] =
                o[i][j] * inv_l;
        }
    }
}

// ---------------------------------------------------------------------------
// Launch
// ---------------------------------------------------------------------------
extern "C" void kernel_launch(void* const* d_in, const int* in_sizes, int n_in,
                              void* d_out, int out_size)
{
    const float* x  = (const float*)d_in[0];
    const float* wq = (const float*)d_in[1];
    const float* wk = (const float*)d_in[2];
    const float* wv = (const float*)d_in[3];
    const float* wo = (const float*)d_in[4];
    float* out = (float*)d_out;

    __nv_bfloat16 *xhi, *xlo, *wqhi, *wqlo, *wkhi, *wklo, *wvhi, *wvlo,
                  *wohi, *wolo, *ohi, *olo;
    float *q, *k, *v, *o;
    cudaGetSymbolAddress((void**)&xhi, g_xhi);
    cudaGetSymbolAddress((void**)&xlo, g_xlo);
    cudaGetSymbolAddress((void**)&wqhi, g_wqhi);
    cudaGetSymbolAddress((void**)&wqlo, g_wqlo);
    cudaGetSymbolAddress((void**)&wkhi, g_wkhi);
    cudaGetSymbolAddress((void**)&wklo, g_wklo);
    cudaGetSymbolAddress((void**)&wvhi, g_wvhi);
    cudaGetSymbolAddress((void**)&wvlo, g_wvlo);
    cudaGetSymbolAddress((void**)&wohi, g_wohi);
    cudaGetSymbolAddress((void**)&wolo, g_wolo);
    cudaGetSymbolAddress((void**)&ohi, g_ohi);
    cudaGetSymbolAddress((void**)&olo, g_olo);
    cudaGetSymbolAddress((void**)&q, g_q);
    cudaGetSymbolAddress((void**)&k, g_k);
    cudaGetSymbolAddress((void**)&v, g_v);
    cudaGetSymbolAddress((void**)&o, g_o);

    cudaFuncSetAttribute(gemm_tc, cudaFuncAttributeMaxDynamicSharedMemorySize,
                         GEMM_SMEM);
    cudaFuncSetAttribute(flash_attn, cudaFuncAttributeMaxDynamicSharedMemorySize,
                         ATT_SMEM_BYTES);

    prep_split<<<NELEM / 4 / 256, 256>>>(x, xhi, xlo, NELEM / 4);
    prep_split<<<W_ELEM / 4 / 256, 256>>>(wq, wqhi, wqlo, W_ELEM / 4);
    prep_split<<<W_ELEM / 4 / 256, 256>>>(wk, wkhi, wklo, W_ELEM / 4);
    prep_split<<<W_ELEM / 4 / 256, 256>>>(wv, wvhi, wvlo, W_ELEM / 4);
    prep_split<<<W_ELEM / 4 / 256, 256>>>(wo, wohi, wolo, W_ELEM / 4);

    dim3 gemmGrid(D_MODEL / 128, M_TOKENS / 128);    // (8, 64)
    gemm_tc<<<gemmGrid, 256, GEMM_SMEM>>>(xhi, xlo, wqhi, wqlo, q, 1);
    gemm_tc<<<gemmGrid, 256, GEMM_SMEM>>>(xhi, xlo, wkhi, wklo, k, 1);
    gemm_tc<<<gemmGrid, 256, GEMM_SMEM>>>(xhi, xlo, wvhi, wvlo, v, 1);

    dim3 attnGrid(SEQ / 64, BATCH * NUM_HEADS);      // (32, 64)
    flash_attn<<<attnGrid, 256, ATT_SMEM_BYTES>>>(q, k, v, o);

    prep_split<<<NELEM / 4 / 256, 256>>>(o, ohi, olo, NELEM / 4);
    gemm_tc<<<gemmGrid, 256, GEMM_SMEM>>>(ohi, olo, wohi, wolo, out, 0);
}

// round 7
// speedup vs baseline: 3.1277x; 2.1171x over previous
#include <cuda_runtime.h>
#include <cuda_bf16.h>
#include <cstdint>

#define D_MODEL   1024
#define NUM_HEADS 16
#define D_K       64
#define BATCH     4
#define SEQ       2048
#define M_TOKENS  (BATCH * SEQ)          // 8192
#define NELEM     (M_TOKENS * D_MODEL)   // 8388608
#define W_ELEM    (D_MODEL * D_MODEL)    // 1048576

// ---------------------------------------------------------------------------
// Scratch (allocation-free)
// ---------------------------------------------------------------------------
__device__ __nv_bfloat16 g_xhi[NELEM],  g_xlo[NELEM];
__device__ __nv_bfloat16 g_wqhi[W_ELEM], g_wqlo[W_ELEM];
__device__ __nv_bfloat16 g_wkhi[W_ELEM], g_wklo[W_ELEM];
__device__ __nv_bfloat16 g_wvhi[W_ELEM], g_wvlo[W_ELEM];
__device__ __nv_bfloat16 g_wohi[W_ELEM], g_wolo[W_ELEM];
__device__ __nv_bfloat16 g_qhi[NELEM],  g_qlo[NELEM];    // [b,h,s,d], pre-scaled
__device__ __nv_bfloat16 g_khi[NELEM],  g_klo[NELEM];    // [b,h,s,d]
__device__ __nv_bfloat16 g_vthi[NELEM], g_vtlo[NELEM];   // [b,h,d,s] (transposed)
__device__ __nv_bfloat16 g_ohi[NELEM],  g_olo[NELEM];    // [tok, 1024]

// ---------------------------------------------------------------------------
// helpers
// ---------------------------------------------------------------------------
__device__ __forceinline__ void mma16816(float* c, const uint32_t* a,
                                         const uint32_t* b)
{
    asm volatile(
        "mma.sync.aligned.m16n8k16.row.col.f32.bf16.bf16.f32 "
        "{%0,%1,%2,%3}, {%4,%5,%6,%7}, {%8,%9}, {%0,%1,%2,%3};"
        : "+f"(c[0]), "+f"(c[1]), "+f"(c[2]), "+f"(c[3])
        : "r"(a[0]), "r"(a[1]), "r"(a[2]), "r"(a[3]),
          "r"(b[0]), "r"(b[1]));
}
__device__ __forceinline__ uint32_t smem_u32(const void* p) {
    uint32_t a;
    asm("{ .reg .u64 t; cvta.to.shared.u64 t, %1; cvt.u32.u64 %0, t; }"
        : "=r"(a) : "l"(p));
    return a;
}
__device__ __forceinline__ void cp_async16(uint32_t dst, const void* src) {
    asm volatile("cp.async.cg.shared.global [%0], [%1], 16;"
                 :: "r"(dst), "l"(src) : "memory");
}
__device__ __forceinline__ void cp_commit() {
    asm volatile("cp.async.commit_group;" ::: "memory");
}
template <int N>
__device__ __forceinline__ void cp_wait() {
    asm volatile("cp.async.wait_group %0;" :: "n"(N) : "memory");
}
// split (x,y) into packed bf16 hi pair and bf16 lo pair
__device__ __forceinline__ void split2(float x, float y,
                                       uint32_t& hi, uint32_t& lo) {
    __nv_bfloat16 hx = __float2bfloat16(x);
    __nv_bfloat16 hy = __float2bfloat16(y);
    __nv_bfloat16 lx = __float2bfloat16(x - __bfloat162float(hx));
    __nv_bfloat16 ly = __float2bfloat16(y - __bfloat162float(hy));
    hi = (uint32_t)__bfloat16_as_ushort(hx) |
         ((uint32_t)__bfloat16_as_ushort(hy) << 16);
    lo = (uint32_t)__bfloat16_as_ushort(lx) |
         ((uint32_t)__bfloat16_as_ushort(ly) << 16);
}

// ---------------------------------------------------------------------------
// fp32 -> (bf16 hi, bf16 lo) split (x and weights only)
// ---------------------------------------------------------------------------
__global__ void prep_split(const float* __restrict__ in,
                           __nv_bfloat16* __restrict__ hi,
                           __nv_bfloat16* __restrict__ lo, int n4)
{
    int i = blockIdx.x * blockDim.x + threadIdx.x;
    if (i >= n4) return;
    float4 f = ((const float4*)in)[i];
    float fv[4] = {f.x, f.y, f.z, f.w};
    __nv_bfloat16 h[4], l[4];
#pragma unroll
    for (int j = 0; j < 4; ++j) {
        h[j] = __float2bfloat16(fv[j]);
        l[j] = __float2bfloat16(fv[j] - __bfloat162float(h[j]));
    }
    ((uint2*)hi)[i] = *(uint2*)h;
    ((uint2*)lo)[i] = *(uint2*)l;
}

// ---------------------------------------------------------------------------
// HMMA GEMM (hi/lo 3-product). CTA 128x128, BK=32, 256 threads.
// mode 0: C fp32 [M,1024]
// mode 1: Q  -> hi/lo bf16 [b,h,s,d], scaled by 0.125
// mode 2: K  -> hi/lo bf16 [b,h,s,d]
// mode 3: V  -> hi/lo bf16 [b,h,d,s] (transposed)
// ---------------------------------------------------------------------------
#define BK        32
#define SROW      40
#define TILE_B    (128 * SROW * 2)
#define STAGE_B   (4 * TILE_B)
#define GEMM_SMEM (2 * STAGE_B)
#define NK_CHUNKS (D_MODEL / BK)

__global__ __launch_bounds__(256, 1)
void gemm_tc(const __nv_bfloat16* __restrict__ Ahi,
             const __nv_bfloat16* __restrict__ Alo,
             const __nv_bfloat16* __restrict__ Bhi,
             const __nv_bfloat16* __restrict__ Blo,
             float* __restrict__ C,
             __nv_bfloat16* __restrict__ Chi,
             __nv_bfloat16* __restrict__ Clo,
             int mode)
{
    extern __shared__ __align__(16) char sm[];

    const int tid  = threadIdx.x;
    const int wid  = tid >> 5;
    const int lane = tid & 31;
    const int grp  = lane >> 2;
    const int qp   = lane & 3;

    const int warp_m = (wid & 1) * 64;
    const int warp_n = (wid >> 1) * 32;

    const int m0 = blockIdx.y * 128;
    const int n0 = blockIdx.x * 128;

    const __nv_bfloat16* srcs[4] = {
        Ahi + (size_t)m0 * D_MODEL, Alo + (size_t)m0 * D_MODEL,
        Bhi + (size_t)n0 * D_MODEL, Blo + (size_t)n0 * D_MODEL
    };

    const uint32_t smbase = smem_u32(sm);

    auto load_stage = [&](int stage, int k0) {
        uint32_t dst0 = smbase + stage * STAGE_B;
#pragma unroll
        for (int a = 0; a < 4; ++a) {
#pragma unroll
            for (int it = 0; it < 2; ++it) {
                int g   = tid + it * 256;
                int row = g >> 2;
                int q   = g & 3;
                const __nv_bfloat16* src = srcs[a] + (size_t)row * D_MODEL + k0 + q * 8;
                cp_async16(dst0 + a * TILE_B + (row * SROW + q * 8) * 2, src);
            }
        }
        cp_commit();
    };

    float acc[4][4][4];
#pragma unroll
    for (int mf = 0; mf < 4; ++mf)
#pragma unroll
        for (int nf = 0; nf < 4; ++nf)
#pragma unroll
            for (int r = 0; r < 4; ++r) acc[mf][nf][r] = 0.0f;

    load_stage(0, 0);
    load_stage(1, BK);

    for (int kc = 0; kc < NK_CHUNKS; ++kc) {
        if (kc < NK_CHUNKS - 2) cp_wait<1>();
        else                    cp_wait<0>();
        __syncthreads();

        const int st = kc & 1;
        const __nv_bfloat16* Ahs = (const __nv_bfloat16*)(sm + st * STAGE_B);
        const __nv_bfloat16* Als = Ahs + 128 * SROW;
        const __nv_bfloat16* Bhs = Als + 128 * SROW;
        const __nv_bfloat16* Bls = Bhs + 128 * SROW;

#pragma unroll
        for (int ks = 0; ks < 2; ++ks) {
            const int kb = ks * 16;
            uint32_t ahi[4][4], alo[4][4], bhi[4][2], blo[4][2];
#pragma unroll
            for (int mf = 0; mf < 4; ++mf) {
                int r0 = warp_m + mf * 16 + grp;
                int c0 = kb + qp * 2;
                ahi[mf][0] = *(const uint32_t*)&Ahs[r0 * SROW + c0];
                ahi[mf][1] = *(const uint32_t*)&Ahs[(r0 + 8) * SROW + c0];
                ahi[mf][2] = *(const uint32_t*)&Ahs[r0 * SROW + c0 + 8];
                ahi[mf][3] = *(const uint32_t*)&Ahs[(r0 + 8) * SROW + c0 + 8];
                alo[mf][0] = *(const uint32_t*)&Als[r0 * SROW + c0];
                alo[mf][1] = *(const uint32_t*)&Als[(r0 + 8) * SROW + c0];
                alo[mf][2] = *(const uint32_t*)&Als[r0 * SROW + c0 + 8];
                alo[mf][3] = *(const uint32_t*)&Als[(r0 + 8) * SROW + c0 + 8];
            }
#pragma unroll
            for (int nf = 0; nf < 4; ++nf) {
                int n = warp_n + nf * 8 + grp;
                int c0 = kb + qp * 2;
                bhi[nf][0] = *(const uint32_t*)&Bhs[n * SROW + c0];
                bhi[nf][1] = *(const uint32_t*)&Bhs[n * SROW + c0 + 8];
                blo[nf][0] = *(const uint32_t*)&Bls[n * SROW + c0];
                blo[nf][1] = *(const uint32_t*)&Bls[n * SROW + c0 + 8];
            }
#pragma unroll
            for (int mf = 0; mf < 4; ++mf)
#pragma unroll
                for (int nf = 0; nf < 4; ++nf) {
                    mma16816(acc[mf][nf], ahi[mf], bhi[nf]);
                    mma16816(acc[mf][nf], ahi[mf], blo[nf]);
                    mma16816(acc[mf][nf], alo[mf], bhi[nf]);
                }
        }
        __syncthreads();
        if (kc + 2 < NK_CHUNKS) load_stage(st, (kc + 2) * BK);
    }

    // Epilogue
    const float scale = (mode == 1) ? 0.125f : 1.0f;
#pragma unroll
    for (int mf = 0; mf < 4; ++mf) {
#pragma unroll
        for (int half = 0; half < 2; ++half) {
            int m = m0 + warp_m + mf * 16 + grp + half * 8;
            int b = m >> 11, s = m & (SEQ - 1);
#pragma unroll
            for (int nf = 0; nf < 4; ++nf) {
                int n = n0 + warp_n + nf * 8 + qp * 2;
                float vx = acc[mf][nf][half * 2];
                float vy = acc[mf][nf][half * 2 + 1];
                if (mode == 0) {
                    *(float2*)&C[(size_t)m * D_MODEL + n] = make_float2(vx, vy);
                } else {
                    int h = n >> 6, d = n & 63;
                    vx *= scale; vy *= scale;
                    uint32_t hp, lp;
                    split2(vx, vy, hp, lp);
                    if (mode != 3) {
                        size_t base = ((size_t)(b * NUM_HEADS + h) * SEQ + s) * D_K + d;
                        *(uint32_t*)&Chi[base] = hp;
                        *(uint32_t*)&Clo[base] = lp;
                    } else {
                        size_t base = ((size_t)(b * NUM_HEADS + h) * D_K + d) * SEQ + s;
                        Chi[base]        = __ushort_as_bfloat16((uint16_t)hp);
                        Clo[base]        = __ushort_as_bfloat16((uint16_t)lp);
                        Chi[base + SEQ]  = __ushort_as_bfloat16((uint16_t)(hp >> 16));
                        Clo[base + SEQ]  = __ushort_as_bfloat16((uint16_t)(lp >> 16));
                    }
                }
            }
        }
    }
}

// ---------------------------------------------------------------------------
// HMMA flash attention (causal, online softmax, bf16 hi/lo 3-product).
// 128 threads (4 warps), BM=64 (16 rows/warp), BN=64. Q pre-scaled.
// K tiles [j][d] row-major; V tiles pre-transposed [d][j]. Both NT-pattern.
// P stays in registers (C-frag -> A-frag identity mapping).
// Output written directly as bf16 hi/lo in merged [tok,1024] layout.
// ---------------------------------------------------------------------------
#define FROW     72                         // 64 + 8 pad (bf16)
#define FTILE    (64 * FROW)                // bf16 elems per tile
#define FSTAGE   (4 * FTILE)                // Khi,Klo,Vthi,Vtlo
#define FA_SMEM  (2 * FSTAGE * 2)           // bytes = 73728

__global__ __launch_bounds__(128, 2)
void flash_tc(const __nv_bfloat16* __restrict__ qhi,
              const __nv_bfloat16* __restrict__ qlo,
              const __nv_bfloat16* __restrict__ khi,
              const __nv_bfloat16* __restrict__ klo,
              const __nv_bfloat16* __restrict__ vthi,
              const __nv_bfloat16* __restrict__ vtlo,
              __nv_bfloat16* __restrict__ ohi,
              __nv_bfloat16* __restrict__ olo)
{
    extern __shared__ __align__(16) __nv_bfloat16 fs[];

    const int tid  = threadIdx.x;
    const int w    = tid >> 5;
    const int lane = tid & 31;
    const int grp  = lane >> 2;
    const int qp   = lane & 3;

    const int bh = blockIdx.y;
    const int b  = bh >> 4;
    const int h  = bh & 15;
    const int i0 = blockIdx.x * 64;

    // Q fragments (pre-scaled by 0.125 in gemm_tc mode 1)
    uint32_t qhf[4][4], qlf[4][4];
    {
        const __nv_bfloat16* qh = qhi + ((size_t)bh * SEQ + i0 + w * 16) * D_K;
        const __nv_bfloat16* ql = qlo + ((size_t)bh * SEQ + i0 + w * 16) * D_K;
#pragma unroll
        for (int kf = 0; kf < 4; ++kf) {
            int c0 = kf * 16 + qp * 2;
            qhf[kf][0] = *(const uint32_t*)&qh[grp * D_K + c0];
            qhf[kf][1] = *(const uint32_t*)&qh[(grp + 8) * D_K + c0];
            qhf[kf][2] = *(const uint32_t*)&qh[grp * D_K + c0 + 8];
            qhf[kf][3] = *(const uint32_t*)&qh[(grp + 8) * D_K + c0 + 8];
            qlf[kf][0] = *(const uint32_t*)&ql[grp * D_K + c0];
            qlf[kf][1] = *(const uint32_t*)&ql[(grp + 8) * D_K + c0];
            qlf[kf][2] = *(const uint32_t*)&ql[grp * D_K + c0 + 8];
            qlf[kf][3] = *(const uint32_t*)&ql[(grp + 8) * D_K + c0 + 8];
        }
    }

    const uint32_t smbase = smem_u32(fs);

    auto load_kv = [&](int stage, int j0) {
        uint32_t dstb = smbase + stage * FSTAGE * 2;
#pragma unroll
        for (int t16 = 0; t16 < 16; ++t16) {
            int c    = tid + t16 * 128;
            int tile = c >> 9;
            int idx  = c & 511;
            int row  = idx >> 3;
            int c8   = idx & 7;
            const __nv_bfloat16* sp;
            if (tile == 0)
                sp = khi  + ((size_t)bh * SEQ + j0 + row) * D_K + c8 * 8;
            else if (tile == 1)
                sp = klo  + ((size_t)bh * SEQ + j0 + row) * D_K + c8 * 8;
            else if (tile == 2)
                sp = vthi + ((size_t)bh * D_K + row) * SEQ + j0 + c8 * 8;
            else
                sp = vtlo + ((size_t)bh * D_K + row) * SEQ + j0 + c8 * 8;
            cp_async16(dstb + (tile * FTILE + row * FROW + c8 * 8) * 2, sp);
        }
        cp_commit();
    };

    float oacc[8][4];
#pragma unroll
    for (int nf = 0; nf < 8; ++nf)
#pragma unroll
        for (int r = 0; r < 4; ++r) oacc[nf][r] = 0.0f;
    float m0v = -1e30f, m1v = -1e30f, l0 = 0.0f, l1 = 0.0f;

    const int nt = i0 / 64 + 1;
    load_kv(0, 0);

    for (int t = 0; t < nt; ++t) {
        const int st = t & 1;
        if (t + 1 < nt) { load_kv(st ^ 1, (t + 1) * 64); cp_wait<1>(); }
        else            { cp_wait<0>(); }
        __syncthreads();

        const __nv_bfloat16* Kh = fs + st * FSTAGE;
        const __nv_bfloat16* Kl = Kh + FTILE;
        const __nv_bfloat16* Vh = Kh + 2 * FTILE;
        const __nv_bfloat16* Vl = Kh + 3 * FTILE;

        // S = Q K^T
        float sacc[8][4];
#pragma unroll
        for (int nf = 0; nf < 8; ++nf)
#pragma unroll
            for (int r = 0; r < 4; ++r) sacc[nf][r] = 0.0f;

#pragma unroll
        for (int nf = 0; nf < 8; ++nf) {
            const int rb = (nf * 8 + grp) * FROW;
#pragma unroll
            for (int kf = 0; kf < 4; ++kf) {
                const int cc = kf * 16 + qp * 2;
                uint32_t bkh[2] = { *(const uint32_t*)&Kh[rb + cc],
                                    *(const uint32_t*)&Kh[rb + cc + 8] };
                uint32_t bkl[2] = { *(const uint32_t*)&Kl[rb + cc],
                                    *(const uint32_t*)&Kl[rb + cc + 8] };
                mma16816(sacc[nf], qhf[kf], bkh);
                mma16816(sacc[nf], qhf[kf], bkl);
                mma16816(sacc[nf], qlf[kf], bkh);
            }
        }

        // causal mask (diagonal tile only)
        if (t == nt - 1) {
            const int r0 = w * 16 + grp;
            const int r1 = r0 + 8;
#pragma unroll
            for (int nf = 0; nf < 8; ++nf) {
                int c0 = nf * 8 + qp * 2;
                if (c0     > r0) sacc[nf][0] = -1e30f;
                if (c0 + 1 > r0) sacc[nf][1] = -1e30f;
                if (c0     > r1) sacc[nf][2] = -1e30f;
                if (c0 + 1 > r1) sacc[nf][3] = -1e30f;
            }
        }

        // row max (own 16 + quad shfl)
        float mx0 = -1e30f, mx1 = -1e30f;
#pragma unroll
        for (int nf = 0; nf < 8; ++nf) {
            mx0 = fmaxf(mx0, fmaxf(sacc[nf][0], sacc[nf][1]));
            mx1 = fmaxf(mx1, fmaxf(sacc[nf][2], sacc[nf][3]));
        }
        mx0 = fmaxf(mx0, __shfl_xor_sync(0xffffffffu, mx0, 1));
        mx0 = fmaxf(mx0, __shfl_xor_sync(0xffffffffu, mx0, 2));
        mx1 = fmaxf(mx1, __shfl_xor_sync(0xffffffffu, mx1, 1));
        mx1 = fmaxf(mx1, __shfl_xor_sync(0xffffffffu, mx1, 2));

        float mn0 = fmaxf(m0v, mx0), mn1 = fmaxf(m1v, mx1);
        float a0 = __expf(m0v - mn0), a1 = __expf(m1v - mn1);
        m0v = mn0; m1v = mn1;

        // P = exp(S - m), split hi/lo, packed as A-fragments
        float s0 = 0.0f, s1 = 0.0f;
        uint32_t ph01[8], ph23[8], pl01[8], pl23[8];
#pragma unroll
        for (int nf = 0; nf < 8; ++nf) {
            float p0 = __expf(sacc[nf][0] - mn0);
            float p1 = __expf(sacc[nf][1] - mn0);
            float p2 = __expf(sacc[nf][2] - mn1);
            float p3 = __expf(sacc[nf][3] - mn1);
            s0 += p0 + p1; s1 += p2 + p3;
            split2(p0, p1, ph01[nf], pl01[nf]);
            split2(p2, p3, ph23[nf], pl23[nf]);
        }
        s0 += __shfl_xor_sync(0xffffffffu, s0, 1);
        s0 += __shfl_xor_sync(0xffffffffu, s0, 2);
        s1 += __shfl_xor_sync(0xffffffffu, s1, 1);
        s1 += __shfl_xor_sync(0xffffffffu, s1, 2);
        l0 = l0 * a0 + s0;
        l1 = l1 * a1 + s1;

#pragma unroll
        for (int nf = 0; nf < 8; ++nf) {
            oacc[nf][0] *= a0; oacc[nf][1] *= a0;
            oacc[nf][2] *= a1; oacc[nf][3] *= a1;
        }

        // O += P V   (Vt tiles: [d][j], NT pattern)
#pragma unroll
        for (int nfd = 0; nfd < 8; ++nfd) {
            const int rb = (nfd * 8 + grp) * FROW;
#pragma unroll
            for (int kf = 0; kf < 4; ++kf) {
                const int cc = kf * 16 + qp * 2;
                uint32_t bvh[2] = { *(const uint32_t*)&Vh[rb + cc],
                                    *(const uint32_t*)&Vh[rb + cc + 8] };
                uint32_t bvl[2] = { *(const uint32_t*)&Vl[rb + cc],
                                    *(const uint32_t*)&Vl[rb + cc + 8] };
                uint32_t ap[4] = { ph01[2 * kf], ph23[2 * kf],
                                   ph01[2 * kf + 1], ph23[2 * kf + 1] };
                uint32_t al[4] = { pl01[2 * kf], pl23[2 * kf],
                                   pl01[2 * kf + 1], pl23[2 * kf + 1] };
                mma16816(oacc[nfd], ap, bvh);
                mma16816(oacc[nfd], ap, bvl);
                mma16816(oacc[nfd], al, bvh);
            }
        }
        __syncthreads();
    }

    // epilogue: normalize, split hi/lo, write merged [tok, h*64+d]
    const float il0 = 1.0f / l0, il1 = 1.0f / l1;
    const size_t tok0 = (size_t)b * SEQ + i0 + w * 16 + grp;
#pragma unroll
    for (int nf = 0; nf < 8; ++nf) {
        int col = h * D_K + nf * 8 + qp * 2;
        uint32_t hp, lp;
        split2(oacc[nf][0] * il0, oacc[nf][1] * il0, hp, lp);
        *(uint32_t*)&ohi[tok0 * D_MODEL + col] = hp;
        *(uint32_t*)&olo[tok0 * D_MODEL + col] = lp;
        split2(oacc[nf][2] * il1, oacc[nf][3] * il1, hp, lp);
        *(uint32_t*)&ohi[(tok0 + 8) * D_MODEL + col] = hp;
        *(uint32_t*)&olo[(tok0 + 8) * D_MODEL + col] = lp;
    }
}

// ---------------------------------------------------------------------------
// Launch
// ---------------------------------------------------------------------------
extern "C" void kernel_launch(void* const* d_in, const int* in_sizes, int n_in,
                              void* d_out, int out_size)
{
    const float* x  = (const float*)d_in[0];
    const float* wq = (const float*)d_in[1];
    const float* wk = (const float*)d_in[2];
    const float* wv = (const float*)d_in[3];
    const float* wo = (const float*)d_in[4];
    float* out = (float*)d_out;

    __nv_bfloat16 *xhi, *xlo, *wqhi, *wqlo, *wkhi, *wklo, *wvhi, *wvlo,
                  *wohi, *wolo, *qhi, *qlo, *khi, *klo, *vthi, *vtlo,
                  *ohi, *olo;
    cudaGetSymbolAddress((void**)&xhi, g_xhi);
    cudaGetSymbolAddress((void**)&xlo, g_xlo);
    cudaGetSymbolAddress((void**)&wqhi, g_wqhi);
    cudaGetSymbolAddress((void**)&wqlo, g_wqlo);
    cudaGetSymbolAddress((void**)&wkhi, g_wkhi);
    cudaGetSymbolAddress((void**)&wklo, g_wklo);
    cudaGetSymbolAddress((void**)&wvhi, g_wvhi);
    cudaGetSymbolAddress((void**)&wvlo, g_wvlo);
    cudaGetSymbolAddress((void**)&wohi, g_wohi);
    cudaGetSymbolAddress((void**)&wolo, g_wolo);
    cudaGetSymbolAddress((void**)&qhi, g_qhi);
    cudaGetSymbolAddress((void**)&qlo, g_qlo);
    cudaGetSymbolAddress((void**)&khi, g_khi);
    cudaGetSymbolAddress((void**)&klo, g_klo);
    cudaGetSymbolAddress((void**)&vthi, g_vthi);
    cudaGetSymbolAddress((void**)&vtlo, g_vtlo);
    cudaGetSymbolAddress((void**)&ohi, g_ohi);
    cudaGetSymbolAddress((void**)&olo, g_olo);

    cudaFuncSetAttribute(gemm_tc, cudaFuncAttributeMaxDynamicSharedMemorySize,
                         GEMM_SMEM);
    cudaFuncSetAttribute(flash_tc, cudaFuncAttributeMaxDynamicSharedMemorySize,
                         FA_SMEM);

    prep_split<<<NELEM / 4 / 256, 256>>>(x, xhi, xlo, NELEM / 4);
    prep_split<<<W_ELEM / 4 / 256, 256>>>(wq, wqhi, wqlo, W_ELEM / 4);
    prep_split<<<W_ELEM / 4 / 256, 256>>>(wk, wkhi, wklo, W_ELEM / 4);
    prep_split<<<W_ELEM / 4 / 256, 256>>>(wv, wvhi, wvlo, W_ELEM / 4);
    prep_split<<<W_ELEM / 4 / 256, 256>>>(wo, wohi, wolo, W_ELEM / 4);

    dim3 gemmGrid(D_MODEL / 128, M_TOKENS / 128);    // (8, 64)
    gemm_tc<<<gemmGrid, 256, GEMM_SMEM>>>(xhi, xlo, wqhi, wqlo,
                                          nullptr, qhi, qlo, 1);
    gemm_tc<<<gemmGrid, 256, GEMM_SMEM>>>(xhi, xlo, wkhi, wklo,
                                          nullptr, khi, klo, 2);
    gemm_tc<<<gemmGrid, 256, GEMM_SMEM>>>(xhi, xlo, wvhi, wvlo,
                                          nullptr, vthi, vtlo, 3);

    dim3 attnGrid(SEQ / 64, BATCH * NUM_HEADS);      // (32, 64)
    flash_tc<<<attnGrid, 128, FA_SMEM>>>(qhi, qlo, khi, klo, vthi, vtlo,
                                         ohi, olo);

    gemm_tc<<<gemmGrid, 256, GEMM_SMEM>>>(ohi, olo, wohi, wolo,
                                          out, nullptr, nullptr, 0);
}